// round 12
// baseline (speedup 1.0000x reference)
#include <cuda_runtime.h>
#include <cuda_fp16.h>
#include <cstdint>

#define T_TOK 4096
#define DDIM  2048
#define NEXP  16
#define IDIM  1408
#define KSEL  4
#define NA    (T_TOK * KSEL)   // 16384 assignments

// ===================== device scratch (static; no cudaMalloc) ===============
__device__ int g_off[NEXP + 1];
__device__ int g_perm[NA];
__device__ __half g_x16[(size_t)T_TOK * DDIM];
__device__ __half g_w0h[(size_t)NEXP * IDIM * DDIM];
__device__ __half g_w0l[(size_t)NEXP * IDIM * DDIM];
__device__ __half g_w1h[(size_t)NEXP * IDIM * DDIM];
__device__ __half g_w1l[(size_t)NEXP * IDIM * DDIM];
__device__ __half g_w2h[(size_t)NEXP * DDIM * IDIM];
__device__ __half g_w2l[(size_t)NEXP * DDIM * IDIM];
// padded by 128 rows so GEMM2 tail-tile loads stay in-bounds
__device__ __half g_h16[(size_t)(NA + 128) * IDIM];

// ===================== asm helpers (compute_103-safe: sm_80 era) ============
__device__ __forceinline__ uint32_t s2u(const void* p) {
    uint32_t a;
    asm("{ .reg .u64 t; cvta.to.shared.u64 t, %1; cvt.u32.u64 %0, t; }" : "=r"(a) : "l"(p));
    return a;
}
#define CPA(dst, src) \
    asm volatile("cp.async.cg.shared.global [%0], [%1], 16;" :: "r"(dst), "l"(src))
#define CPC()  asm volatile("cp.async.commit_group;" ::: "memory")
#define CPW0() asm volatile("cp.async.wait_group 0;" ::: "memory")
#define CPW1() asm volatile("cp.async.wait_group 1;" ::: "memory")

__device__ __forceinline__ void ldm_x4(uint32_t* r, uint32_t a) {
    asm volatile("ldmatrix.sync.aligned.m8n8.x4.shared.b16 {%0,%1,%2,%3}, [%4];"
                 : "=r"(r[0]), "=r"(r[1]), "=r"(r[2]), "=r"(r[3]) : "r"(a));
}
__device__ __forceinline__ void mma16816(float* d, const uint32_t* a, const uint32_t* b) {
    asm volatile(
        "mma.sync.aligned.m16n8k16.row.col.f32.f16.f16.f32 "
        "{%0,%1,%2,%3}, {%4,%5,%6,%7}, {%8,%9}, {%0,%1,%2,%3};"
        : "+f"(d[0]), "+f"(d[1]), "+f"(d[2]), "+f"(d[3])
        : "r"(a[0]), "r"(a[1]), "r"(a[2]), "r"(a[3]), "r"(b[0]), "r"(b[1]));
}

// smem row pitch: 40 fp16 = 80 bytes -> ldmatrix rows hit banks
// (20*r)%32 = {0,20,8,28,16,4,24,12}: conflict-free.
#define PB 80

// ===================== routing ==============================================
__global__ void route_kernel(const int* __restrict__ sel) {
    __shared__ int s_cnt[NEXP];
    __shared__ int s_cur[NEXP];
    int tid = threadIdx.x;
    if (tid < NEXP) s_cnt[tid] = 0;
    __syncthreads();
    for (int i = tid; i < NA; i += blockDim.x)
        atomicAdd(&s_cnt[sel[i]], 1);
    __syncthreads();
    if (tid == 0) {
        int acc = 0;
        for (int e = 0; e < NEXP; e++) { g_off[e] = acc; s_cur[e] = acc; acc += s_cnt[e]; }
        g_off[NEXP] = acc;
    }
    __syncthreads();
    for (int i = tid; i < NA; i += blockDim.x) {
        int pos = atomicAdd(&s_cur[sel[i]], 1);
        g_perm[pos] = i;
    }
}

// ===================== fp32 -> fp16 convert =================================
// x: single fp16 (round). w0/w1/w2: fp16 hi + fp16 lo (2-term split).
#define NX4  ((T_TOK * (size_t)DDIM) / 4)
#define NW4  (((size_t)NEXP * IDIM * DDIM) / 4)
#define NCVT (NX4 + 3 * NW4)

__device__ __forceinline__ uint32_t pkh2(__half a, __half b) {
    __half2 t = __halves2half2(a, b);
    return *(uint32_t*)&t;
}

__global__ __launch_bounds__(256) void cvt_all(const float4* __restrict__ x4,
                                               const float4* __restrict__ w04,
                                               const float4* __restrict__ w14,
                                               const float4* __restrict__ w24) {
    size_t i = (size_t)blockIdx.x * 256 + threadIdx.x;
    if (i < NX4) {
        float4 v = x4[i];
        uint2 H;
        H.x = pkh2(__float2half_rn(v.x), __float2half_rn(v.y));
        H.y = pkh2(__float2half_rn(v.z), __float2half_rn(v.w));
        ((uint2*)g_x16)[i] = H;
        return;
    }
    const float4* src; uint2* hi; uint2* lo; size_t o;
    if (i < NX4 + NW4)        { src = w04; hi = (uint2*)g_w0h; lo = (uint2*)g_w0l; o = i - NX4; }
    else if (i < NX4 + 2*NW4) { src = w14; hi = (uint2*)g_w1h; lo = (uint2*)g_w1l; o = i - NX4 - NW4; }
    else                      { src = w24; hi = (uint2*)g_w2h; lo = (uint2*)g_w2l; o = i - NX4 - 2*NW4; }
    float4 v = src[o];
    __half h0 = __float2half_rn(v.x), h1 = __float2half_rn(v.y);
    __half h2 = __float2half_rn(v.z), h3 = __float2half_rn(v.w);
    __half l0 = __float2half_rn(v.x - __half2float(h0));
    __half l1 = __float2half_rn(v.y - __half2float(h1));
    __half l2 = __float2half_rn(v.z - __half2float(h2));
    __half l3 = __float2half_rn(v.w - __half2float(h3));
    uint2 H; H.x = pkh2(h0, h1); H.y = pkh2(h2, h3);
    uint2 L; L.x = pkh2(l0, l1); L.y = pkh2(l2, l3);
    hi[o] = H; lo[o] = L;
}

// ===================== GEMM1: H = silu(X w0^T) .* (X w1^T) ==================
// block tile: 128 rows x 64 I-cols, BK=32, 3-stage cp.async (issue depth 2).
// stage: A 10240 | B0h 5120 | B0l 5120 | B1h 5120 | B1l 5120 = 30720
#define G1_A   0
#define G1_B0H 10240
#define G1_B0L 15360
#define G1_B1H 20480
#define G1_B1L 25600
#define G1_STG 30720
#define G1_SMEM (3 * G1_STG + 512)
#define G1_NCH (DDIM / 32)    // 64

__global__ __launch_bounds__(256) void gemm1_mma() {
    const int e     = blockIdx.z;
    const int base  = g_off[e];
    const int count = g_off[e + 1] - base;
    const int row0  = blockIdx.y * 128;
    if (row0 >= count) return;
    const int n0 = blockIdx.x * 64;

    extern __shared__ char smem[];
    const uint32_t sbase = s2u(smem);
    int* s_tok = (int*)(smem + 3 * G1_STG);

    const int tid  = threadIdx.x;
    const int lane = tid & 31, wid = tid >> 5;
    const int warpM = wid >> 2, warpN = wid & 3;

    if (tid < 128) {
        int r = row0 + tid;
        s_tok[tid] = (r < count) ? (g_perm[base + r] >> 2) : 0;
    }
    __syncthreads();

    // cp.async geometry: A 128x32 fp16 (2 chunks/thread), each B mat (1/thread)
    const __half* pA[2];
    uint32_t dA[2];
    #pragma unroll
    for (int j = 0; j < 2; j++) {
        int v = tid + j * 256, r = v >> 2, c = v & 3;
        pA[j] = g_x16 + (size_t)s_tok[r] * DDIM + c * 8;
        dA[j] = r * PB + c * 16;
    }
    const int rB = tid >> 2, cB = tid & 3;
    const size_t oB = (size_t)(n0 + rB) * DDIM + cB * 8;
    const uint32_t dB = rB * PB + cB * 16;
    const __half* w0h_e = g_w0h + (size_t)e * IDIM * DDIM;
    const __half* w0l_e = g_w0l + (size_t)e * IDIM * DDIM;
    const __half* w1h_e = g_w1h + (size_t)e * IDIM * DDIM;
    const __half* w1l_e = g_w1l + (size_t)e * IDIM * DDIM;

    float acc0[4][2][4], acc1[4][2][4];
    #pragma unroll
    for (int mt = 0; mt < 4; mt++)
        #pragma unroll
        for (int nt = 0; nt < 2; nt++)
            #pragma unroll
            for (int q = 0; q < 4; q++) { acc0[mt][nt][q] = 0.f; acc1[mt][nt][q] = 0.f; }

    auto issue = [&](int st, int kc) {
        const uint32_t sb = sbase + st * G1_STG;
        const int ko = kc * 32;
        #pragma unroll
        for (int j = 0; j < 2; j++)
            CPA(sb + G1_A + dA[j], pA[j] + ko);
        CPA(sb + G1_B0H + dB, w0h_e + oB + ko);
        CPA(sb + G1_B0L + dB, w0l_e + oB + ko);
        CPA(sb + G1_B1H + dB, w1h_e + oB + ko);
        CPA(sb + G1_B1L + dB, w1l_e + oB + ko);
        CPC();
    };

    // B ldmatrix x4 merge: matrices [r,klo],[r,khi],[r+8,klo],[r+8,khi]
    const int bRow = warpN * 16 + (lane & 7) + ((lane & 16) >> 1);
    const int bColSel = (lane & 8) ? 8 : 0;

    issue(0, 0);
    issue(1, 1);
    int stage = 0;
    for (int kc = 0; kc < G1_NCH; kc++) {
        if (kc + 1 < G1_NCH) CPW1(); else CPW0();   // chunk kc's group landed
        __syncthreads();        // all warps done reading stage of kc-1
        if (kc + 2 < G1_NCH) {  // refill that stage (= (kc+2)%3)
            int ns = stage + 2; if (ns >= 3) ns -= 3;
            issue(ns, kc + 2);
        }
        const uint32_t sb = sbase + stage * G1_STG;
        #pragma unroll
        for (int ks = 0; ks < 2; ks++) {
            uint32_t bh[4][2], bl[4][2];
            {
                const uint32_t off = bRow * PB + (ks * 16 + bColSel) * 2;
                uint32_t t[4];
                ldm_x4(t, sb + G1_B0H + off);
                bh[0][0] = t[0]; bh[0][1] = t[1]; bh[1][0] = t[2]; bh[1][1] = t[3];
                ldm_x4(t, sb + G1_B0L + off);
                bl[0][0] = t[0]; bl[0][1] = t[1]; bl[1][0] = t[2]; bl[1][1] = t[3];
                ldm_x4(t, sb + G1_B1H + off);
                bh[2][0] = t[0]; bh[2][1] = t[1]; bh[3][0] = t[2]; bh[3][1] = t[3];
                ldm_x4(t, sb + G1_B1L + off);
                bl[2][0] = t[0]; bl[2][1] = t[1]; bl[3][0] = t[2]; bl[3][1] = t[3];
            }
            const int arow = warpM * 64 + (lane & 15);
            const int acol = ks * 16 + ((lane >> 4) << 3);
            #pragma unroll
            for (int mt = 0; mt < 4; mt++) {
                uint32_t a[4];
                ldm_x4(a, sb + G1_A + (arow + mt * 16) * PB + acol * 2);
                #pragma unroll
                for (int nt = 0; nt < 4; nt++) {
                    float* d = (nt < 2) ? acc0[mt][nt] : acc1[mt][nt - 2];
                    mma16816(d, a, bh[nt]);
                }
                #pragma unroll
                for (int nt = 0; nt < 4; nt++) {
                    float* d = (nt < 2) ? acc0[mt][nt] : acc1[mt][nt - 2];
                    mma16816(d, a, bl[nt]);
                }
            }
        }
        if (++stage == 3) stage = 0;
    }

    // epilogue: h = silu(u0) * u1 -> single fp16
    #pragma unroll
    for (int mt = 0; mt < 4; mt++) {
        #pragma unroll
        for (int rr = 0; rr < 2; rr++) {
            const int row = row0 + warpM * 64 + mt * 16 + (lane >> 2) + rr * 8;
            if (row < count) {
                const size_t ro = (size_t)(base + row) * IDIM;
                #pragma unroll
                for (int nt = 0; nt < 2; nt++) {
                    const int col = n0 + warpN * 16 + nt * 8 + (lane & 3) * 2;
                    float u0a = acc0[mt][nt][rr * 2 + 0], u0b = acc0[mt][nt][rr * 2 + 1];
                    float u1a = acc1[mt][nt][rr * 2 + 0], u1b = acc1[mt][nt][rr * 2 + 1];
                    float ha = (u0a / (1.f + __expf(-u0a))) * u1a;
                    float hb = (u0b / (1.f + __expf(-u0b))) * u1b;
                    *(uint32_t*)(g_h16 + ro + col) =
                        pkh2(__float2half_rn(ha), __float2half_rn(hb));
                }
            }
        }
    }
}

// ===================== GEMM2: OUT = (H w2^T) * rw ===========================
// block tile: 128 rows x 128 D-cols, BK=32 over I, 3-stage cp.async.
// stage: A 10240 | Bh 10240 | Bl 10240 = 30720
#define G2_A  0
#define G2_BH 10240
#define G2_BL 20480
#define G2_STG 30720
#define G2_SMEM (3 * G2_STG + 512)
#define G2_NCH (IDIM / 32)   // 44

__global__ __launch_bounds__(256) void gemm2_mma(const float* __restrict__ rw,
                                                 float* __restrict__ out) {
    const int e     = blockIdx.z;
    const int base  = g_off[e];
    const int count = g_off[e + 1] - base;
    const int row0  = blockIdx.y * 128;
    if (row0 >= count) return;
    const int n0 = blockIdx.x * 128;

    extern __shared__ char smem[];
    const uint32_t sbase = s2u(smem);
    int* s_pack = (int*)(smem + 3 * G2_STG);

    const int tid  = threadIdx.x;
    const int lane = tid & 31, wid = tid >> 5;
    const int warpM = wid >> 2, warpN = wid & 3;

    if (tid < 128) {
        int r = row0 + tid;
        s_pack[tid] = (r < count) ? g_perm[base + r] : -1;
    }
    __syncthreads();

    // cp.async geometry: A 128x32 (2/thread), Bh/Bl 128x32 (2/thread each)
    const __half* pA[2];
    uint32_t dA[2];
    size_t oBv[2];
    #pragma unroll
    for (int j = 0; j < 2; j++) {
        int v = tid + j * 256, r = v >> 2, c = v & 3;
        pA[j] = g_h16 + (size_t)(base + row0 + r) * IDIM + c * 8;
        dA[j] = r * PB + c * 16;
        oBv[j] = (size_t)(n0 + r) * IDIM + c * 8;
    }
    const __half* w2h_e = g_w2h + (size_t)e * DDIM * IDIM;
    const __half* w2l_e = g_w2l + (size_t)e * DDIM * IDIM;

    float acc[4][4][4];
    #pragma unroll
    for (int mt = 0; mt < 4; mt++)
        #pragma unroll
        for (int nt = 0; nt < 4; nt++)
            #pragma unroll
            for (int q = 0; q < 4; q++) acc[mt][nt][q] = 0.f;

    auto issue = [&](int st, int kc) {
        const uint32_t sb = sbase + st * G2_STG;
        const int ko = kc * 32;
        #pragma unroll
        for (int j = 0; j < 2; j++) {
            CPA(sb + G2_A  + dA[j], pA[j] + ko);
            CPA(sb + G2_BH + dA[j], w2h_e + oBv[j] + ko);
            CPA(sb + G2_BL + dA[j], w2l_e + oBv[j] + ko);
        }
        CPC();
    };

    // B x4 merge: matrices [r,klo],[r,khi],[r+8,klo],[r+8,khi]
    const int bRow = warpN * 32 + (lane & 7) + ((lane & 16) >> 1);
    const int bColSel = (lane & 8) ? 8 : 0;

    issue(0, 0);
    issue(1, 1);
    int stage = 0;
    for (int kc = 0; kc < G2_NCH; kc++) {
        if (kc + 1 < G2_NCH) CPW1(); else CPW0();
        __syncthreads();
        if (kc + 2 < G2_NCH) {
            int ns = stage + 2; if (ns >= 3) ns -= 3;
            issue(ns, kc + 2);
        }
        const uint32_t sb = sbase + stage * G2_STG;
        #pragma unroll
        for (int ks = 0; ks < 2; ks++) {
            uint32_t bh[4][2], bl[4][2];
            {
                const uint32_t off0 = bRow * PB + (ks * 16 + bColSel) * 2;
                const uint32_t off1 = off0 + 16 * PB;   // nt pair {2,3}: rows +16
                uint32_t t[4];
                ldm_x4(t, sb + G2_BH + off0);
                bh[0][0] = t[0]; bh[0][1] = t[1]; bh[1][0] = t[2]; bh[1][1] = t[3];
                ldm_x4(t, sb + G2_BL + off0);
                bl[0][0] = t[0]; bl[0][1] = t[1]; bl[1][0] = t[2]; bl[1][1] = t[3];
                ldm_x4(t, sb + G2_BH + off1);
                bh[2][0] = t[0]; bh[2][1] = t[1]; bh[3][0] = t[2]; bh[3][1] = t[3];
                ldm_x4(t, sb + G2_BL + off1);
                bl[2][0] = t[0]; bl[2][1] = t[1]; bl[3][0] = t[2]; bl[3][1] = t[3];
            }
            const int arow = warpM * 64 + (lane & 15);
            const int acol = ks * 16 + ((lane >> 4) << 3);
            #pragma unroll
            for (int mt = 0; mt < 4; mt++) {
                uint32_t a[4];
                ldm_x4(a, sb + G2_A + (arow + mt * 16) * PB + acol * 2);
                #pragma unroll
                for (int nt = 0; nt < 4; nt++) mma16816(acc[mt][nt], a, bh[nt]);
                #pragma unroll
                for (int nt = 0; nt < 4; nt++) mma16816(acc[mt][nt], a, bl[nt]);
            }
        }
        if (++stage == 3) stage = 0;
    }

    // epilogue: scale by routing weight, scatter to out[pack]
    #pragma unroll
    for (int mt = 0; mt < 4; mt++) {
        #pragma unroll
        for (int rr = 0; rr < 2; rr++) {
            const int lrow = warpM * 64 + mt * 16 + (lane >> 2) + rr * 8;
            const int pack = s_pack[lrow];
            if (pack >= 0) {
                const float w = rw[pack];
                float* fo = out + (size_t)pack * DDIM + n0;
                #pragma unroll
                for (int nt = 0; nt < 4; nt++) {
                    const int col = warpN * 32 + nt * 8 + (lane & 3) * 2;
                    float2 o2;
                    o2.x = acc[mt][nt][rr * 2 + 0] * w;
                    o2.y = acc[mt][nt][rr * 2 + 1] * w;
                    *(float2*)(fo + col) = o2;
                }
            }
        }
    }
}

// ===================== launch ===============================================
extern "C" void kernel_launch(void* const* d_in, const int* in_sizes, int n_in,
                              void* d_out, int out_size) {
    const float* x   = (const float*)d_in[0];
    const float* w0  = (const float*)d_in[1];
    const float* w1  = (const float*)d_in[2];
    const float* w2  = (const float*)d_in[3];
    const int*   sel = (const int*)  d_in[4];
    const float* rw  = (const float*)d_in[5];
    float*       out = (float*)d_out;

    cudaFuncSetAttribute(gemm1_mma, cudaFuncAttributeMaxDynamicSharedMemorySize, G1_SMEM);
    cudaFuncSetAttribute(gemm2_mma, cudaFuncAttributeMaxDynamicSharedMemorySize, G2_SMEM);

    route_kernel<<<1, 256>>>(sel);

    cvt_all<<<(unsigned)(NCVT / 256), 256>>>((const float4*)x, (const float4*)w0,
                                             (const float4*)w1, (const float4*)w2);

    dim3 g1(IDIM / 64, NA / 128, NEXP);    // 22 x 128 x 16
    gemm1_mma<<<g1, 256, G1_SMEM>>>();

    dim3 g2(DDIM / 128, NA / 128, NEXP);   // 16 x 128 x 16
    gemm2_mma<<<g2, 256, G2_SMEM>>>(rw, out);
}

// round 14
// speedup vs baseline: 1.2870x; 1.2870x over previous
#include <cuda_runtime.h>
#include <cuda_fp16.h>
#include <cstdint>

#define T_TOK 4096
#define DDIM  2048
#define NEXP  16
#define IDIM  1408
#define KSEL  4
#define NA    (T_TOK * KSEL)   // 16384 assignments

// ===================== device scratch (static; no cudaMalloc) ===============
__device__ int g_off[NEXP + 1];
__device__ int g_perm[NA];
__device__ __half g_x16[(size_t)T_TOK * DDIM];
__device__ __half g_w0[(size_t)NEXP * IDIM * DDIM];   // single fp16
__device__ __half g_w1[(size_t)NEXP * IDIM * DDIM];   // single fp16
__device__ __half g_w2h[(size_t)NEXP * DDIM * IDIM];  // 2-term split
__device__ __half g_w2l[(size_t)NEXP * DDIM * IDIM];
// padded by 128 rows so GEMM2 tail-tile loads stay in-bounds
__device__ __half g_h16[(size_t)(NA + 128) * IDIM];

// ===================== asm helpers (compute_103-safe: sm_80 era) ============
__device__ __forceinline__ uint32_t s2u(const void* p) {
    uint32_t a;
    asm("{ .reg .u64 t; cvta.to.shared.u64 t, %1; cvt.u32.u64 %0, t; }" : "=r"(a) : "l"(p));
    return a;
}
#define CPA(dst, src) \
    asm volatile("cp.async.cg.shared.global [%0], [%1], 16;" :: "r"(dst), "l"(src))
#define CPC()  asm volatile("cp.async.commit_group;" ::: "memory")
#define CPW0() asm volatile("cp.async.wait_group 0;" ::: "memory")

__device__ __forceinline__ void ldm_x4(uint32_t* r, uint32_t a) {
    asm volatile("ldmatrix.sync.aligned.m8n8.x4.shared.b16 {%0,%1,%2,%3}, [%4];"
                 : "=r"(r[0]), "=r"(r[1]), "=r"(r[2]), "=r"(r[3]) : "r"(a));
}
__device__ __forceinline__ void mma16816(float* d, const uint32_t* a, const uint32_t* b) {
    asm volatile(
        "mma.sync.aligned.m16n8k16.row.col.f32.f16.f16.f32 "
        "{%0,%1,%2,%3}, {%4,%5,%6,%7}, {%8,%9}, {%0,%1,%2,%3};"
        : "+f"(d[0]), "+f"(d[1]), "+f"(d[2]), "+f"(d[3])
        : "r"(a[0]), "r"(a[1]), "r"(a[2]), "r"(a[3]), "r"(b[0]), "r"(b[1]));
}

// smem row pitch: 40 fp16 = 80 bytes -> ldmatrix rows hit banks
// (20*r)%32 = {0,20,8,28,16,4,24,12}: conflict-free.
#define PB 80

// ===================== routing ==============================================
__global__ void route_kernel(const int* __restrict__ sel) {
    __shared__ int s_cnt[NEXP];
    __shared__ int s_cur[NEXP];
    int tid = threadIdx.x;
    if (tid < NEXP) s_cnt[tid] = 0;
    __syncthreads();
    for (int i = tid; i < NA; i += blockDim.x)
        atomicAdd(&s_cnt[sel[i]], 1);
    __syncthreads();
    if (tid == 0) {
        int acc = 0;
        for (int e = 0; e < NEXP; e++) { g_off[e] = acc; s_cur[e] = acc; acc += s_cnt[e]; }
        g_off[NEXP] = acc;
    }
    __syncthreads();
    for (int i = tid; i < NA; i += blockDim.x) {
        int pos = atomicAdd(&s_cur[sel[i]], 1);
        g_perm[pos] = i;
    }
}

// ===================== fp32 -> fp16 convert =================================
// x, w0, w1: single fp16 (round). w2: fp16 hi + fp16 lo (2-term split).
#define NX4  ((T_TOK * (size_t)DDIM) / 4)
#define NW4  (((size_t)NEXP * IDIM * DDIM) / 4)
#define NCVT (NX4 + 3 * NW4)

__device__ __forceinline__ uint32_t pkh2(__half a, __half b) {
    __half2 t = __halves2half2(a, b);
    return *(uint32_t*)&t;
}

__global__ __launch_bounds__(256) void cvt_all(const float4* __restrict__ x4,
                                               const float4* __restrict__ w04,
                                               const float4* __restrict__ w14,
                                               const float4* __restrict__ w24) {
    size_t i = (size_t)blockIdx.x * 256 + threadIdx.x;
    if (i < NX4 + 2 * NW4) {
        const float4* src; uint2* dst; size_t o;
        if (i < NX4)            { src = x4;  dst = (uint2*)g_x16; o = i; }
        else if (i < NX4 + NW4) { src = w04; dst = (uint2*)g_w0;  o = i - NX4; }
        else                    { src = w14; dst = (uint2*)g_w1;  o = i - NX4 - NW4; }
        float4 v = src[o];
        uint2 H;
        H.x = pkh2(__float2half_rn(v.x), __float2half_rn(v.y));
        H.y = pkh2(__float2half_rn(v.z), __float2half_rn(v.w));
        dst[o] = H;
        return;
    }
    size_t o = i - NX4 - 2 * NW4;
    float4 v = w24[o];
    __half h0 = __float2half_rn(v.x), h1 = __float2half_rn(v.y);
    __half h2 = __float2half_rn(v.z), h3 = __float2half_rn(v.w);
    __half l0 = __float2half_rn(v.x - __half2float(h0));
    __half l1 = __float2half_rn(v.y - __half2float(h1));
    __half l2 = __float2half_rn(v.z - __half2float(h2));
    __half l3 = __float2half_rn(v.w - __half2float(h3));
    uint2 H; H.x = pkh2(h0, h1); H.y = pkh2(h2, h3);
    uint2 L; L.x = pkh2(l0, l1); L.y = pkh2(l2, l3);
    ((uint2*)g_w2h)[o] = H; ((uint2*)g_w2l)[o] = L;
}

// ===================== GEMM1: H = silu(X w0^T) .* (X w1^T) ==================
// block tile: 128 rows x 64 I-cols, BK=32, 2-stage cp.async. Single-term w.
// stage: A 10240 | B0 5120 | B1 5120 = 20480
#define G1_A  0
#define G1_B0 10240
#define G1_B1 15360
#define G1_STG 20480
#define G1_SMEM (2 * G1_STG + 512)
#define G1_NCH (DDIM / 32)    // 64

__global__ __launch_bounds__(256) void gemm1_mma() {
    const int e     = blockIdx.z;
    const int base  = g_off[e];
    const int count = g_off[e + 1] - base;
    const int row0  = blockIdx.y * 128;
    if (row0 >= count) return;
    const int n0 = blockIdx.x * 64;

    extern __shared__ char smem[];
    const uint32_t sbase = s2u(smem);
    int* s_tok = (int*)(smem + 2 * G1_STG);

    const int tid  = threadIdx.x;
    const int lane = tid & 31, wid = tid >> 5;
    const int warpM = wid >> 2, warpN = wid & 3;

    if (tid < 128) {
        int r = row0 + tid;
        s_tok[tid] = (r < count) ? (g_perm[base + r] >> 2) : 0;
    }
    __syncthreads();

    // cp.async geometry: A 128x32 fp16 (2 chunks/thread), each B mat (1/thread)
    const __half* pA[2];
    uint32_t dA[2];
    #pragma unroll
    for (int j = 0; j < 2; j++) {
        int v = tid + j * 256, r = v >> 2, c = v & 3;
        pA[j] = g_x16 + (size_t)s_tok[r] * DDIM + c * 8;
        dA[j] = r * PB + c * 16;
    }
    const int rB = tid >> 2, cB = tid & 3;
    const size_t oB = (size_t)(n0 + rB) * DDIM + cB * 8;
    const uint32_t dB = rB * PB + cB * 16;
    const __half* w0_e = g_w0 + (size_t)e * IDIM * DDIM;
    const __half* w1_e = g_w1 + (size_t)e * IDIM * DDIM;

    float acc0[4][2][4], acc1[4][2][4];
    #pragma unroll
    for (int mt = 0; mt < 4; mt++)
        #pragma unroll
        for (int nt = 0; nt < 2; nt++)
            #pragma unroll
            for (int q = 0; q < 4; q++) { acc0[mt][nt][q] = 0.f; acc1[mt][nt][q] = 0.f; }

    auto issue = [&](int st, int kc) {
        const uint32_t sb = sbase + st * G1_STG;
        const int ko = kc * 32;
        #pragma unroll
        for (int j = 0; j < 2; j++)
            CPA(sb + G1_A + dA[j], pA[j] + ko);
        CPA(sb + G1_B0 + dB, w0_e + oB + ko);
        CPA(sb + G1_B1 + dB, w1_e + oB + ko);
        CPC();
    };

    // B ldmatrix x4 merge: matrices [r,klo],[r,khi],[r+8,klo],[r+8,khi]
    const int bRow = warpN * 16 + (lane & 7) + ((lane & 16) >> 1);
    const int bColSel = (lane & 8) ? 8 : 0;

    issue(0, 0);
    for (int kc = 0; kc < G1_NCH; kc++) {
        const int s = kc & 1;
        CPW0();
        __syncthreads();
        if (kc + 1 < G1_NCH) issue(s ^ 1, kc + 1);   // overlaps compute below
        const uint32_t sb = sbase + s * G1_STG;
        #pragma unroll
        for (int ks = 0; ks < 2; ks++) {
            uint32_t b[4][2];
            {
                const uint32_t off = bRow * PB + (ks * 16 + bColSel) * 2;
                uint32_t t[4];
                ldm_x4(t, sb + G1_B0 + off);
                b[0][0] = t[0]; b[0][1] = t[1]; b[1][0] = t[2]; b[1][1] = t[3];
                ldm_x4(t, sb + G1_B1 + off);
                b[2][0] = t[0]; b[2][1] = t[1]; b[3][0] = t[2]; b[3][1] = t[3];
            }
            const int arow = warpM * 64 + (lane & 15);
            const int acol = ks * 16 + ((lane >> 4) << 3);
            #pragma unroll
            for (int mt = 0; mt < 4; mt++) {
                uint32_t a[4];
                ldm_x4(a, sb + G1_A + (arow + mt * 16) * PB + acol * 2);
                #pragma unroll
                for (int nt = 0; nt < 4; nt++) {
                    float* d = (nt < 2) ? acc0[mt][nt] : acc1[mt][nt - 2];
                    mma16816(d, a, b[nt]);
                }
            }
        }
    }

    // epilogue: h = silu(u0) * u1 -> single fp16
    #pragma unroll
    for (int mt = 0; mt < 4; mt++) {
        #pragma unroll
        for (int rr = 0; rr < 2; rr++) {
            const int row = row0 + warpM * 64 + mt * 16 + (lane >> 2) + rr * 8;
            if (row < count) {
                const size_t ro = (size_t)(base + row) * IDIM;
                #pragma unroll
                for (int nt = 0; nt < 2; nt++) {
                    const int col = n0 + warpN * 16 + nt * 8 + (lane & 3) * 2;
                    float u0a = acc0[mt][nt][rr * 2 + 0], u0b = acc0[mt][nt][rr * 2 + 1];
                    float u1a = acc1[mt][nt][rr * 2 + 0], u1b = acc1[mt][nt][rr * 2 + 1];
                    float ha = (u0a / (1.f + __expf(-u0a))) * u1a;
                    float hb = (u0b / (1.f + __expf(-u0b))) * u1b;
                    *(uint32_t*)(g_h16 + ro + col) =
                        pkh2(__float2half_rn(ha), __float2half_rn(hb));
                }
            }
        }
    }
}

// ===================== GEMM2: OUT = (H w2^T) * rw ===========================
// block tile: 128 rows x 128 D-cols, BK=32 over I, 2-stage cp.async, 2-term w2.
// stage: A 10240 | Bh 10240 | Bl 10240 = 30720
#define G2_A  0
#define G2_BH 10240
#define G2_BL 20480
#define G2_STG 30720
#define G2_SMEM (2 * G2_STG + 512)
#define G2_NCH (IDIM / 32)   // 44

__global__ __launch_bounds__(256) void gemm2_mma(const float* __restrict__ rw,
                                                 float* __restrict__ out) {
    const int e     = blockIdx.z;
    const int base  = g_off[e];
    const int count = g_off[e + 1] - base;
    const int row0  = blockIdx.y * 128;
    if (row0 >= count) return;
    const int n0 = blockIdx.x * 128;

    extern __shared__ char smem[];
    const uint32_t sbase = s2u(smem);
    int* s_pack = (int*)(smem + 2 * G2_STG);

    const int tid  = threadIdx.x;
    const int lane = tid & 31, wid = tid >> 5;
    const int warpM = wid >> 2, warpN = wid & 3;

    if (tid < 128) {
        int r = row0 + tid;
        s_pack[tid] = (r < count) ? g_perm[base + r] : -1;
    }
    __syncthreads();

    // cp.async geometry: A 128x32 (2/thread), Bh/Bl 128x32 (2/thread each)
    const __half* pA[2];
    uint32_t dA[2];
    size_t oBv[2];
    #pragma unroll
    for (int j = 0; j < 2; j++) {
        int v = tid + j * 256, r = v >> 2, c = v & 3;
        pA[j] = g_h16 + (size_t)(base + row0 + r) * IDIM + c * 8;
        dA[j] = r * PB + c * 16;
        oBv[j] = (size_t)(n0 + r) * IDIM + c * 8;
    }
    const __half* w2h_e = g_w2h + (size_t)e * DDIM * IDIM;
    const __half* w2l_e = g_w2l + (size_t)e * DDIM * IDIM;

    float acc[4][4][4];
    #pragma unroll
    for (int mt = 0; mt < 4; mt++)
        #pragma unroll
        for (int nt = 0; nt < 4; nt++)
            #pragma unroll
            for (int q = 0; q < 4; q++) acc[mt][nt][q] = 0.f;

    auto issue = [&](int st, int kc) {
        const uint32_t sb = sbase + st * G2_STG;
        const int ko = kc * 32;
        #pragma unroll
        for (int j = 0; j < 2; j++) {
            CPA(sb + G2_A  + dA[j], pA[j] + ko);
            CPA(sb + G2_BH + dA[j], w2h_e + oBv[j] + ko);
            CPA(sb + G2_BL + dA[j], w2l_e + oBv[j] + ko);
        }
        CPC();
    };

    // B x4 merge: matrices [r,klo],[r,khi],[r+8,klo],[r+8,khi]
    const int bRow = warpN * 32 + (lane & 7) + ((lane & 16) >> 1);
    const int bColSel = (lane & 8) ? 8 : 0;

    issue(0, 0);
    for (int kc = 0; kc < G2_NCH; kc++) {
        const int s = kc & 1;
        CPW0();
        __syncthreads();
        if (kc + 1 < G2_NCH) issue(s ^ 1, kc + 1);
        const uint32_t sb = sbase + s * G2_STG;
        #pragma unroll
        for (int ks = 0; ks < 2; ks++) {
            uint32_t bh[4][2], bl[4][2];
            {
                const uint32_t off0 = bRow * PB + (ks * 16 + bColSel) * 2;
                const uint32_t off1 = off0 + 16 * PB;   // nt pair {2,3}: rows +16
                uint32_t t[4];
                ldm_x4(t, sb + G2_BH + off0);
                bh[0][0] = t[0]; bh[0][1] = t[1]; bh[1][0] = t[2]; bh[1][1] = t[3];
                ldm_x4(t, sb + G2_BL + off0);
                bl[0][0] = t[0]; bl[0][1] = t[1]; bl[1][0] = t[2]; bl[1][1] = t[3];
                ldm_x4(t, sb + G2_BH + off1);
                bh[2][0] = t[0]; bh[2][1] = t[1]; bh[3][0] = t[2]; bh[3][1] = t[3];
                ldm_x4(t, sb + G2_BL + off1);
                bl[2][0] = t[0]; bl[2][1] = t[1]; bl[3][0] = t[2]; bl[3][1] = t[3];
            }
            const int arow = warpM * 64 + (lane & 15);
            const int acol = ks * 16 + ((lane >> 4) << 3);
            #pragma unroll
            for (int mt = 0; mt < 4; mt++) {
                uint32_t a[4];
                ldm_x4(a, sb + G2_A + (arow + mt * 16) * PB + acol * 2);
                #pragma unroll
                for (int nt = 0; nt < 4; nt++) mma16816(acc[mt][nt], a, bh[nt]);
                #pragma unroll
                for (int nt = 0; nt < 4; nt++) mma16816(acc[mt][nt], a, bl[nt]);
            }
        }
    }

    // epilogue: scale by routing weight, scatter to out[pack]
    #pragma unroll
    for (int mt = 0; mt < 4; mt++) {
        #pragma unroll
        for (int rr = 0; rr < 2; rr++) {
            const int lrow = warpM * 64 + mt * 16 + (lane >> 2) + rr * 8;
            const int pack = s_pack[lrow];
            if (pack >= 0) {
                const float w = rw[pack];
                float* fo = out + (size_t)pack * DDIM + n0;
                #pragma unroll
                for (int nt = 0; nt < 4; nt++) {
                    const int col = warpN * 32 + nt * 8 + (lane & 3) * 2;
                    float2 o2;
                    o2.x = acc[mt][nt][rr * 2 + 0] * w;
                    o2.y = acc[mt][nt][rr * 2 + 1] * w;
                    *(float2*)(fo + col) = o2;
                }
            }
        }
    }
}

// ===================== launch ===============================================
extern "C" void kernel_launch(void* const* d_in, const int* in_sizes, int n_in,
                              void* d_out, int out_size) {
    const float* x   = (const float*)d_in[0];
    const float* w0  = (const float*)d_in[1];
    const float* w1  = (const float*)d_in[2];
    const float* w2  = (const float*)d_in[3];
    const int*   sel = (const int*)  d_in[4];
    const float* rw  = (const float*)d_in[5];
    float*       out = (float*)d_out;

    cudaFuncSetAttribute(gemm1_mma, cudaFuncAttributeMaxDynamicSharedMemorySize, G1_SMEM);
    cudaFuncSetAttribute(gemm2_mma, cudaFuncAttributeMaxDynamicSharedMemorySize, G2_SMEM);

    route_kernel<<<1, 256>>>(sel);

    cvt_all<<<(unsigned)(NCVT / 256), 256>>>((const float4*)x, (const float4*)w0,
                                             (const float4*)w1, (const float4*)w2);

    dim3 g1(IDIM / 64, NA / 128, NEXP);    // 22 x 128 x 16
    gemm1_mma<<<g1, 256, G1_SMEM>>>();

    dim3 g2(DDIM / 128, NA / 128, NEXP);   // 16 x 128 x 16
    gemm2_mma<<<g2, 256, G2_SMEM>>>(rw, out);
}

// round 15
// speedup vs baseline: 1.5095x; 1.1729x over previous
#include <cuda_runtime.h>
#include <cuda_fp16.h>
#include <cstdint>

#define T_TOK 4096
#define DDIM  2048
#define NEXP  16
#define IDIM  1408
#define KSEL  4
#define NA    (T_TOK * KSEL)   // 16384 assignments

// ===================== device scratch (static; no cudaMalloc) ===============
__device__ int g_off[NEXP + 1];
__device__ int g_perm[NA];
__device__ __half g_x16[(size_t)T_TOK * DDIM];
__device__ __half g_w0[(size_t)NEXP * IDIM * DDIM];   // single fp16
__device__ __half g_w1[(size_t)NEXP * IDIM * DDIM];   // single fp16
__device__ __half g_w2[(size_t)NEXP * DDIM * IDIM];   // single fp16
// padded by 128 rows so GEMM2 tail-tile loads stay in-bounds
__device__ __half g_h16[(size_t)(NA + 128) * IDIM];

// ===================== asm helpers (compute_103-safe: sm_80 era) ============
__device__ __forceinline__ uint32_t s2u(const void* p) {
    uint32_t a;
    asm("{ .reg .u64 t; cvta.to.shared.u64 t, %1; cvt.u32.u64 %0, t; }" : "=r"(a) : "l"(p));
    return a;
}
#define CPA(dst, src) \
    asm volatile("cp.async.cg.shared.global [%0], [%1], 16;" :: "r"(dst), "l"(src))
#define CPC()  asm volatile("cp.async.commit_group;" ::: "memory")
#define CPW0() asm volatile("cp.async.wait_group 0;" ::: "memory")

__device__ __forceinline__ void ldm_x4(uint32_t* r, uint32_t a) {
    asm volatile("ldmatrix.sync.aligned.m8n8.x4.shared.b16 {%0,%1,%2,%3}, [%4];"
                 : "=r"(r[0]), "=r"(r[1]), "=r"(r[2]), "=r"(r[3]) : "r"(a));
}
__device__ __forceinline__ void mma16816(float* d, const uint32_t* a, const uint32_t* b) {
    asm volatile(
        "mma.sync.aligned.m16n8k16.row.col.f32.f16.f16.f32 "
        "{%0,%1,%2,%3}, {%4,%5,%6,%7}, {%8,%9}, {%0,%1,%2,%3};"
        : "+f"(d[0]), "+f"(d[1]), "+f"(d[2]), "+f"(d[3])
        : "r"(a[0]), "r"(a[1]), "r"(a[2]), "r"(a[3]), "r"(b[0]), "r"(b[1]));
}

// smem row pitch: 40 fp16 = 80 bytes -> ldmatrix rows hit banks
// (20*r)%32 = {0,20,8,28,16,4,24,12}: conflict-free.
#define PB 80

// ===================== routing ==============================================
__global__ void route_kernel(const int* __restrict__ sel) {
    __shared__ int s_cnt[NEXP];
    __shared__ int s_cur[NEXP];
    int tid = threadIdx.x;
    if (tid < NEXP) s_cnt[tid] = 0;
    __syncthreads();
    for (int i = tid; i < NA; i += blockDim.x)
        atomicAdd(&s_cnt[sel[i]], 1);
    __syncthreads();
    if (tid == 0) {
        int acc = 0;
        for (int e = 0; e < NEXP; e++) { g_off[e] = acc; s_cur[e] = acc; acc += s_cnt[e]; }
        g_off[NEXP] = acc;
    }
    __syncthreads();
    for (int i = tid; i < NA; i += blockDim.x) {
        int pos = atomicAdd(&s_cur[sel[i]], 1);
        g_perm[pos] = i;
    }
}

// ===================== fp32 -> fp16 convert (all single fp16) ===============
#define NX4  ((T_TOK * (size_t)DDIM) / 4)
#define NW4  (((size_t)NEXP * IDIM * DDIM) / 4)
#define NCVT (NX4 + 3 * NW4)

__device__ __forceinline__ uint32_t pkh2(__half a, __half b) {
    __half2 t = __halves2half2(a, b);
    return *(uint32_t*)&t;
}

__global__ __launch_bounds__(256) void cvt_all(const float4* __restrict__ x4,
                                               const float4* __restrict__ w04,
                                               const float4* __restrict__ w14,
                                               const float4* __restrict__ w24) {
    size_t i = (size_t)blockIdx.x * 256 + threadIdx.x;
    const float4* src; uint2* dst; size_t o;
    if (i < NX4)              { src = x4;  dst = (uint2*)g_x16; o = i; }
    else if (i < NX4 + NW4)   { src = w04; dst = (uint2*)g_w0;  o = i - NX4; }
    else if (i < NX4 + 2*NW4) { src = w14; dst = (uint2*)g_w1;  o = i - NX4 - NW4; }
    else                      { src = w24; dst = (uint2*)g_w2;  o = i - NX4 - 2*NW4; }
    float4 v = src[o];
    uint2 H;
    H.x = pkh2(__float2half_rn(v.x), __float2half_rn(v.y));
    H.y = pkh2(__float2half_rn(v.z), __float2half_rn(v.w));
    dst[o] = H;
}

// ===================== GEMM1: H = silu(X w0^T) .* (X w1^T) ==================
// block tile: 128 rows x 64 I-cols, BK=32, 2-stage cp.async. Single-term w.
// stage: A 10240 | B0 5120 | B1 5120 = 20480
#define G1_A  0
#define G1_B0 10240
#define G1_B1 15360
#define G1_STG 20480
#define G1_SMEM (2 * G1_STG + 512)
#define G1_NCH (DDIM / 32)    // 64

__global__ __launch_bounds__(256) void gemm1_mma() {
    const int e     = blockIdx.z;
    const int base  = g_off[e];
    const int count = g_off[e + 1] - base;
    const int row0  = blockIdx.y * 128;
    if (row0 >= count) return;
    const int n0 = blockIdx.x * 64;

    extern __shared__ char smem[];
    const uint32_t sbase = s2u(smem);
    int* s_tok = (int*)(smem + 2 * G1_STG);

    const int tid  = threadIdx.x;
    const int lane = tid & 31, wid = tid >> 5;
    const int warpM = wid >> 2, warpN = wid & 3;

    if (tid < 128) {
        int r = row0 + tid;
        s_tok[tid] = (r < count) ? (g_perm[base + r] >> 2) : 0;
    }
    __syncthreads();

    // cp.async geometry: A 128x32 fp16 (2 chunks/thread), each B mat (1/thread)
    const __half* pA[2];
    uint32_t dA[2];
    #pragma unroll
    for (int j = 0; j < 2; j++) {
        int v = tid + j * 256, r = v >> 2, c = v & 3;
        pA[j] = g_x16 + (size_t)s_tok[r] * DDIM + c * 8;
        dA[j] = r * PB + c * 16;
    }
    const int rB = tid >> 2, cB = tid & 3;
    const size_t oB = (size_t)(n0 + rB) * DDIM + cB * 8;
    const uint32_t dB = rB * PB + cB * 16;
    const __half* w0_e = g_w0 + (size_t)e * IDIM * DDIM;
    const __half* w1_e = g_w1 + (size_t)e * IDIM * DDIM;

    float acc0[4][2][4], acc1[4][2][4];
    #pragma unroll
    for (int mt = 0; mt < 4; mt++)
        #pragma unroll
        for (int nt = 0; nt < 2; nt++)
            #pragma unroll
            for (int q = 0; q < 4; q++) { acc0[mt][nt][q] = 0.f; acc1[mt][nt][q] = 0.f; }

    auto issue = [&](int st, int kc) {
        const uint32_t sb = sbase + st * G1_STG;
        const int ko = kc * 32;
        #pragma unroll
        for (int j = 0; j < 2; j++)
            CPA(sb + G1_A + dA[j], pA[j] + ko);
        CPA(sb + G1_B0 + dB, w0_e + oB + ko);
        CPA(sb + G1_B1 + dB, w1_e + oB + ko);
        CPC();
    };

    // B ldmatrix x4 merge: matrices [r,klo],[r,khi],[r+8,klo],[r+8,khi]
    const int bRow = warpN * 16 + (lane & 7) + ((lane & 16) >> 1);
    const int bColSel = (lane & 8) ? 8 : 0;

    issue(0, 0);
    for (int kc = 0; kc < G1_NCH; kc++) {
        const int s = kc & 1;
        CPW0();
        __syncthreads();
        if (kc + 1 < G1_NCH) issue(s ^ 1, kc + 1);   // overlaps compute below
        const uint32_t sb = sbase + s * G1_STG;
        #pragma unroll
        for (int ks = 0; ks < 2; ks++) {
            uint32_t b[4][2];
            {
                const uint32_t off = bRow * PB + (ks * 16 + bColSel) * 2;
                uint32_t t[4];
                ldm_x4(t, sb + G1_B0 + off);
                b[0][0] = t[0]; b[0][1] = t[1]; b[1][0] = t[2]; b[1][1] = t[3];
                ldm_x4(t, sb + G1_B1 + off);
                b[2][0] = t[0]; b[2][1] = t[1]; b[3][0] = t[2]; b[3][1] = t[3];
            }
            const int arow = warpM * 64 + (lane & 15);
            const int acol = ks * 16 + ((lane >> 4) << 3);
            #pragma unroll
            for (int mt = 0; mt < 4; mt++) {
                uint32_t a[4];
                ldm_x4(a, sb + G1_A + (arow + mt * 16) * PB + acol * 2);
                #pragma unroll
                for (int nt = 0; nt < 4; nt++) {
                    float* d = (nt < 2) ? acc0[mt][nt] : acc1[mt][nt - 2];
                    mma16816(d, a, b[nt]);
                }
            }
        }
    }

    // epilogue: h = silu(u0) * u1 -> single fp16
    #pragma unroll
    for (int mt = 0; mt < 4; mt++) {
        #pragma unroll
        for (int rr = 0; rr < 2; rr++) {
            const int row = row0 + warpM * 64 + mt * 16 + (lane >> 2) + rr * 8;
            if (row < count) {
                const size_t ro = (size_t)(base + row) * IDIM;
                #pragma unroll
                for (int nt = 0; nt < 2; nt++) {
                    const int col = n0 + warpN * 16 + nt * 8 + (lane & 3) * 2;
                    float u0a = acc0[mt][nt][rr * 2 + 0], u0b = acc0[mt][nt][rr * 2 + 1];
                    float u1a = acc1[mt][nt][rr * 2 + 0], u1b = acc1[mt][nt][rr * 2 + 1];
                    float ha = (u0a / (1.f + __expf(-u0a))) * u1a;
                    float hb = (u0b / (1.f + __expf(-u0b))) * u1b;
                    *(uint32_t*)(g_h16 + ro + col) =
                        pkh2(__float2half_rn(ha), __float2half_rn(hb));
                }
            }
        }
    }
}

// ===================== GEMM2: OUT = (H w2^T) * rw ===========================
// block tile: 128 rows x 128 D-cols, BK=32 over I, 2-stage cp.async, 1-term w2.
// stage: A 10240 | B 10240 = 20480
#define G2_A  0
#define G2_B  10240
#define G2_STG 20480
#define G2_SMEM (2 * G2_STG + 512)
#define G2_NCH (IDIM / 32)   // 44

__global__ __launch_bounds__(256) void gemm2_mma(const float* __restrict__ rw,
                                                 float* __restrict__ out) {
    const int e     = blockIdx.z;
    const int base  = g_off[e];
    const int count = g_off[e + 1] - base;
    const int row0  = blockIdx.y * 128;
    if (row0 >= count) return;
    const int n0 = blockIdx.x * 128;

    extern __shared__ char smem[];
    const uint32_t sbase = s2u(smem);
    int* s_pack = (int*)(smem + 2 * G2_STG);

    const int tid  = threadIdx.x;
    const int lane = tid & 31, wid = tid >> 5;
    const int warpM = wid >> 2, warpN = wid & 3;

    if (tid < 128) {
        int r = row0 + tid;
        s_pack[tid] = (r < count) ? g_perm[base + r] : -1;
    }
    __syncthreads();

    // cp.async geometry: A 128x32 (2/thread), B 128x32 (2/thread)
    const __half* pA[2];
    uint32_t dA[2];
    size_t oBv[2];
    #pragma unroll
    for (int j = 0; j < 2; j++) {
        int v = tid + j * 256, r = v >> 2, c = v & 3;
        pA[j] = g_h16 + (size_t)(base + row0 + r) * IDIM + c * 8;
        dA[j] = r * PB + c * 16;
        oBv[j] = (size_t)(n0 + r) * IDIM + c * 8;
    }
    const __half* w2_e = g_w2 + (size_t)e * DDIM * IDIM;

    float acc[4][4][4];
    #pragma unroll
    for (int mt = 0; mt < 4; mt++)
        #pragma unroll
        for (int nt = 0; nt < 4; nt++)
            #pragma unroll
            for (int q = 0; q < 4; q++) acc[mt][nt][q] = 0.f;

    auto issue = [&](int st, int kc) {
        const uint32_t sb = sbase + st * G2_STG;
        const int ko = kc * 32;
        #pragma unroll
        for (int j = 0; j < 2; j++) {
            CPA(sb + G2_A + dA[j], pA[j] + ko);
            CPA(sb + G2_B + dA[j], w2_e + oBv[j] + ko);
        }
        CPC();
    };

    // B x4 merge: matrices [r,klo],[r,khi],[r+8,klo],[r+8,khi]
    const int bRow = warpN * 32 + (lane & 7) + ((lane & 16) >> 1);
    const int bColSel = (lane & 8) ? 8 : 0;

    issue(0, 0);
    for (int kc = 0; kc < G2_NCH; kc++) {
        const int s = kc & 1;
        CPW0();
        __syncthreads();
        if (kc + 1 < G2_NCH) issue(s ^ 1, kc + 1);
        const uint32_t sb = sbase + s * G2_STG;
        #pragma unroll
        for (int ks = 0; ks < 2; ks++) {
            uint32_t b[4][2];
            {
                const uint32_t off0 = bRow * PB + (ks * 16 + bColSel) * 2;
                const uint32_t off1 = off0 + 16 * PB;   // nt pair {2,3}: rows +16
                uint32_t t[4];
                ldm_x4(t, sb + G2_B + off0);
                b[0][0] = t[0]; b[0][1] = t[1]; b[1][0] = t[2]; b[1][1] = t[3];
                ldm_x4(t, sb + G2_B + off1);
                b[2][0] = t[0]; b[2][1] = t[1]; b[3][0] = t[2]; b[3][1] = t[3];
            }
            const int arow = warpM * 64 + (lane & 15);
            const int acol = ks * 16 + ((lane >> 4) << 3);
            #pragma unroll
            for (int mt = 0; mt < 4; mt++) {
                uint32_t a[4];
                ldm_x4(a, sb + G2_A + (arow + mt * 16) * PB + acol * 2);
                #pragma unroll
                for (int nt = 0; nt < 4; nt++) mma16816(acc[mt][nt], a, b[nt]);
            }
        }
    }

    // epilogue: scale by routing weight, scatter to out[pack]
    #pragma unroll
    for (int mt = 0; mt < 4; mt++) {
        #pragma unroll
        for (int rr = 0; rr < 2; rr++) {
            const int lrow = warpM * 64 + mt * 16 + (lane >> 2) + rr * 8;
            const int pack = s_pack[lrow];
            if (pack >= 0) {
                const float w = rw[pack];
                float* fo = out + (size_t)pack * DDIM + n0;
                #pragma unroll
                for (int nt = 0; nt < 4; nt++) {
                    const int col = warpN * 32 + nt * 8 + (lane & 3) * 2;
                    float2 o2;
                    o2.x = acc[mt][nt][rr * 2 + 0] * w;
                    o2.y = acc[mt][nt][rr * 2 + 1] * w;
                    *(float2*)(fo + col) = o2;
                }
            }
        }
    }
}

// ===================== launch ===============================================
extern "C" void kernel_launch(void* const* d_in, const int* in_sizes, int n_in,
                              void* d_out, int out_size) {
    const float* x   = (const float*)d_in[0];
    const float* w0  = (const float*)d_in[1];
    const float* w1  = (const float*)d_in[2];
    const float* w2  = (const float*)d_in[3];
    const int*   sel = (const int*)  d_in[4];
    const float* rw  = (const float*)d_in[5];
    float*       out = (float*)d_out;

    cudaFuncSetAttribute(gemm1_mma, cudaFuncAttributeMaxDynamicSharedMemorySize, G1_SMEM);
    cudaFuncSetAttribute(gemm2_mma, cudaFuncAttributeMaxDynamicSharedMemorySize, G2_SMEM);

    route_kernel<<<1, 256>>>(sel);

    cvt_all<<<(unsigned)(NCVT / 256), 256>>>((const float4*)x, (const float4*)w0,
                                             (const float4*)w1, (const float4*)w2);

    dim3 g1(IDIM / 64, NA / 128, NEXP);    // 22 x 128 x 16
    gemm1_mma<<<g1, 256, G1_SMEM>>>();

    dim3 g2(DDIM / 128, NA / 128, NEXP);   // 16 x 128 x 16
    gemm2_mma<<<g2, 256, G2_SMEM>>>(rw, out);
}

// round 17
// speedup vs baseline: 1.6854x; 1.1165x over previous
#include <cuda_runtime.h>
#include <cuda_fp16.h>
#include <cstdint>

#define T_TOK 4096
#define DDIM  2048
#define NEXP  16
#define IDIM  1408
#define KSEL  4
#define NA    (T_TOK * KSEL)   // 16384 assignments

// ===================== device scratch (static; no cudaMalloc) ===============
__device__ int g_off[NEXP + 1];
__device__ int g_perm[NA];
__device__ __half g_x16[(size_t)T_TOK * DDIM];
__device__ __half g_w0[(size_t)NEXP * IDIM * DDIM];   // single fp16
__device__ __half g_w1[(size_t)NEXP * IDIM * DDIM];   // single fp16
__device__ __half g_w2[(size_t)NEXP * DDIM * IDIM];   // single fp16
// padded by 128 rows so GEMM2 tail-tile loads stay in-bounds
__device__ __half g_h16[(size_t)(NA + 128) * IDIM];

// ===================== asm helpers (compute_103-safe: sm_80 era) ============
__device__ __forceinline__ uint32_t s2u(const void* p) {
    uint32_t a;
    asm("{ .reg .u64 t; cvta.to.shared.u64 t, %1; cvt.u32.u64 %0, t; }" : "=r"(a) : "l"(p));
    return a;
}
#define CPA(dst, src) \
    asm volatile("cp.async.cg.shared.global [%0], [%1], 16;" :: "r"(dst), "l"(src))
#define CPC()  asm volatile("cp.async.commit_group;" ::: "memory")
#define CPW0() asm volatile("cp.async.wait_group 0;" ::: "memory")

__device__ __forceinline__ void ldm_x4(uint32_t* r, uint32_t a) {
    asm volatile("ldmatrix.sync.aligned.m8n8.x4.shared.b16 {%0,%1,%2,%3}, [%4];"
                 : "=r"(r[0]), "=r"(r[1]), "=r"(r[2]), "=r"(r[3]) : "r"(a));
}
__device__ __forceinline__ void mma16816(float* d, const uint32_t* a, const uint32_t* b) {
    asm volatile(
        "mma.sync.aligned.m16n8k16.row.col.f32.f16.f16.f32 "
        "{%0,%1,%2,%3}, {%4,%5,%6,%7}, {%8,%9}, {%0,%1,%2,%3};"
        : "+f"(d[0]), "+f"(d[1]), "+f"(d[2]), "+f"(d[3])
        : "r"(a[0]), "r"(a[1]), "r"(a[2]), "r"(a[3]), "r"(b[0]), "r"(b[1]));
}

// BK=64: smem row = 64 fp16 = 128B, padded pitch 144B (9 x 16B units).
// Row r's 16B units sit at unit-bank (9r + u) mod 8 -> 8 consecutive rows
// hit 8 distinct banks for any fixed u: ldmatrix conflict-free.
#define PB 144

// ===================== routing ==============================================
__global__ void route_kernel(const int* __restrict__ sel) {
    __shared__ int s_cnt[NEXP];
    __shared__ int s_cur[NEXP];
    int tid = threadIdx.x;
    if (tid < NEXP) s_cnt[tid] = 0;
    __syncthreads();
    for (int i = tid; i < NA; i += blockDim.x)
        atomicAdd(&s_cnt[sel[i]], 1);
    __syncthreads();
    if (tid == 0) {
        int acc = 0;
        for (int e = 0; e < NEXP; e++) { g_off[e] = acc; s_cur[e] = acc; acc += s_cnt[e]; }
        g_off[NEXP] = acc;
    }
    __syncthreads();
    for (int i = tid; i < NA; i += blockDim.x) {
        int pos = atomicAdd(&s_cur[sel[i]], 1);
        g_perm[pos] = i;
    }
}

// ===================== fp32 -> fp16 convert (all single fp16) ===============
#define NX4  ((T_TOK * (size_t)DDIM) / 4)
#define NW4  (((size_t)NEXP * IDIM * DDIM) / 4)
#define NCVT (NX4 + 3 * NW4)

__device__ __forceinline__ uint32_t pkh2(__half a, __half b) {
    __half2 t = __halves2half2(a, b);
    return *(uint32_t*)&t;
}

__global__ __launch_bounds__(256) void cvt_all(const float4* __restrict__ x4,
                                               const float4* __restrict__ w04,
                                               const float4* __restrict__ w14,
                                               const float4* __restrict__ w24) {
    size_t i = (size_t)blockIdx.x * 256 + threadIdx.x;
    const float4* src; uint2* dst; size_t o;
    if (i < NX4)              { src = x4;  dst = (uint2*)g_x16; o = i; }
    else if (i < NX4 + NW4)   { src = w04; dst = (uint2*)g_w0;  o = i - NX4; }
    else if (i < NX4 + 2*NW4) { src = w14; dst = (uint2*)g_w1;  o = i - NX4 - NW4; }
    else                      { src = w24; dst = (uint2*)g_w2;  o = i - NX4 - 2*NW4; }
    float4 v = src[o];
    uint2 H;
    H.x = pkh2(__float2half_rn(v.x), __float2half_rn(v.y));
    H.y = pkh2(__float2half_rn(v.z), __float2half_rn(v.w));
    dst[o] = H;
}

// ===================== GEMM1: H = silu(X w0^T) .* (X w1^T) ==================
// block tile: 128 rows x 64 I-cols, BK=64, 2-stage cp.async. Single-term w.
// stage: A 128x144B = 18432 | B0 64x144B = 9216 | B1 9216 = 36864
#define G1_A  0
#define G1_B0 18432
#define G1_B1 27648
#define G1_STG 36864
#define G1_SMEM (2 * G1_STG + 512)
#define G1_NCH (DDIM / 64)    // 32

__global__ __launch_bounds__(256) void gemm1_mma() {
    const int e     = blockIdx.z;
    const int base  = g_off[e];
    const int count = g_off[e + 1] - base;
    const int row0  = blockIdx.y * 128;
    if (row0 >= count) return;
    const int n0 = blockIdx.x * 64;

    extern __shared__ char smem[];
    const uint32_t sbase = s2u(smem);
    int* s_tok = (int*)(smem + 2 * G1_STG);

    const int tid  = threadIdx.x;
    const int lane = tid & 31, wid = tid >> 5;
    const int warpM = wid >> 2, warpN = wid & 3;

    if (tid < 128) {
        int r = row0 + tid;
        s_tok[tid] = (r < count) ? (g_perm[base + r] >> 2) : 0;
    }
    __syncthreads();

    // cp.async geometry: A 128 rows x 8 units (4/thread); B0/B1 64 rows x 8 (2/thr)
    const __half* pA[4];
    uint32_t dA[4];
    #pragma unroll
    for (int j = 0; j < 4; j++) {
        int v = tid + j * 256, r = v >> 3, u = v & 7;
        pA[j] = g_x16 + (size_t)s_tok[r] * DDIM + u * 8;
        dA[j] = r * PB + u * 16;
    }
    size_t oB[2]; uint32_t dB[2];
    #pragma unroll
    for (int j = 0; j < 2; j++) {
        int v = tid + j * 256, r = v >> 3, u = v & 7;
        oB[j] = (size_t)(n0 + r) * DDIM + u * 8;
        dB[j] = r * PB + u * 16;
    }
    const __half* w0_e = g_w0 + (size_t)e * IDIM * DDIM;
    const __half* w1_e = g_w1 + (size_t)e * IDIM * DDIM;

    float acc0[4][2][4], acc1[4][2][4];
    #pragma unroll
    for (int mt = 0; mt < 4; mt++)
        #pragma unroll
        for (int nt = 0; nt < 2; nt++)
            #pragma unroll
            for (int q = 0; q < 4; q++) { acc0[mt][nt][q] = 0.f; acc1[mt][nt][q] = 0.f; }

    auto issue = [&](int st, int kc) {
        const uint32_t sb = sbase + st * G1_STG;
        const int ko = kc * 64;
        #pragma unroll
        for (int j = 0; j < 4; j++)
            CPA(sb + G1_A + dA[j], pA[j] + ko);
        #pragma unroll
        for (int j = 0; j < 2; j++) {
            CPA(sb + G1_B0 + dB[j], w0_e + oB[j] + ko);
            CPA(sb + G1_B1 + dB[j], w1_e + oB[j] + ko);
        }
        CPC();
    };

    // B ldmatrix x4 merge: matrices [r,klo],[r,khi],[r+8,klo],[r+8,khi]
    const int bRow = warpN * 16 + (lane & 7) + ((lane & 16) >> 1);
    const int bColSel = (lane & 8) ? 8 : 0;

    issue(0, 0);
    for (int kc = 0; kc < G1_NCH; kc++) {
        const int s = kc & 1;
        CPW0();
        __syncthreads();
        if (kc + 1 < G1_NCH) issue(s ^ 1, kc + 1);   // overlaps compute below
        const uint32_t sb = sbase + s * G1_STG;
        #pragma unroll
        for (int ks = 0; ks < 4; ks++) {
            uint32_t b[4][2];
            {
                const uint32_t off = bRow * PB + (ks * 16 + bColSel) * 2;
                uint32_t t[4];
                ldm_x4(t, sb + G1_B0 + off);
                b[0][0] = t[0]; b[0][1] = t[1]; b[1][0] = t[2]; b[1][1] = t[3];
                ldm_x4(t, sb + G1_B1 + off);
                b[2][0] = t[0]; b[2][1] = t[1]; b[3][0] = t[2]; b[3][1] = t[3];
            }
            const int arow = warpM * 64 + (lane & 15);
            const int acol = ks * 16 + ((lane >> 4) << 3);
            #pragma unroll
            for (int mt = 0; mt < 4; mt++) {
                uint32_t a[4];
                ldm_x4(a, sb + G1_A + (arow + mt * 16) * PB + acol * 2);
                #pragma unroll
                for (int nt = 0; nt < 4; nt++) {
                    float* d = (nt < 2) ? acc0[mt][nt] : acc1[mt][nt - 2];
                    mma16816(d, a, b[nt]);
                }
            }
        }
    }

    // epilogue: h = silu(u0) * u1 -> single fp16
    #pragma unroll
    for (int mt = 0; mt < 4; mt++) {
        #pragma unroll
        for (int rr = 0; rr < 2; rr++) {
            const int row = row0 + warpM * 64 + mt * 16 + (lane >> 2) + rr * 8;
            if (row < count) {
                const size_t ro = (size_t)(base + row) * IDIM;
                #pragma unroll
                for (int nt = 0; nt < 2; nt++) {
                    const int col = n0 + warpN * 16 + nt * 8 + (lane & 3) * 2;
                    float u0a = acc0[mt][nt][rr * 2 + 0], u0b = acc0[mt][nt][rr * 2 + 1];
                    float u1a = acc1[mt][nt][rr * 2 + 0], u1b = acc1[mt][nt][rr * 2 + 1];
                    float ha = (u0a / (1.f + __expf(-u0a))) * u1a;
                    float hb = (u0b / (1.f + __expf(-u0b))) * u1b;
                    *(uint32_t*)(g_h16 + ro + col) =
                        pkh2(__float2half_rn(ha), __float2half_rn(hb));
                }
            }
        }
    }
}

// ===================== GEMM2: OUT = (H w2^T) * rw ===========================
// block tile: 128 rows x 128 D-cols, BK=64 over I, 2-stage cp.async, 1-term w2.
// stage: A 128x144B = 18432 | B 128x144B = 18432 = 36864
#define G2_A  0
#define G2_B  18432
#define G2_STG 36864
#define G2_SMEM (2 * G2_STG + 512)
#define G2_NCH (IDIM / 64)   // 22

__global__ __launch_bounds__(256) void gemm2_mma(const float* __restrict__ rw,
                                                 float* __restrict__ out) {
    const int e     = blockIdx.z;
    const int base  = g_off[e];
    const int count = g_off[e + 1] - base;
    const int row0  = blockIdx.y * 128;
    if (row0 >= count) return;
    const int n0 = blockIdx.x * 128;

    extern __shared__ char smem[];
    const uint32_t sbase = s2u(smem);
    int* s_pack = (int*)(smem + 2 * G2_STG);

    const int tid  = threadIdx.x;
    const int lane = tid & 31, wid = tid >> 5;
    const int warpM = wid >> 2, warpN = wid & 3;

    if (tid < 128) {
        int r = row0 + tid;
        s_pack[tid] = (r < count) ? g_perm[base + r] : -1;
    }
    __syncthreads();

    // cp.async geometry: A 128 rows x 8 units (4/thread); B 128 rows (4/thread)
    const __half* pA[4];
    uint32_t dA[4];
    size_t oBv[4];
    #pragma unroll
    for (int j = 0; j < 4; j++) {
        int v = tid + j * 256, r = v >> 3, u = v & 7;
        pA[j] = g_h16 + (size_t)(base + row0 + r) * IDIM + u * 8;
        dA[j] = r * PB + u * 16;
        oBv[j] = (size_t)(n0 + r) * IDIM + u * 8;
    }
    const __half* w2_e = g_w2 + (size_t)e * DDIM * IDIM;

    float acc[4][4][4];
    #pragma unroll
    for (int mt = 0; mt < 4; mt++)
        #pragma unroll
        for (int nt = 0; nt < 4; nt++)
            #pragma unroll
            for (int q = 0; q < 4; q++) acc[mt][nt][q] = 0.f;

    auto issue = [&](int st, int kc) {
        const uint32_t sb = sbase + st * G2_STG;
        const int ko = kc * 64;
        #pragma unroll
        for (int j = 0; j < 4; j++) {
            CPA(sb + G2_A + dA[j], pA[j] + ko);
            CPA(sb + G2_B + dA[j], w2_e + oBv[j] + ko);
        }
        CPC();
    };

    // B x4 merge: matrices [r,klo],[r,khi],[r+8,klo],[r+8,khi]
    const int bRow = warpN * 32 + (lane & 7) + ((lane & 16) >> 1);
    const int bColSel = (lane & 8) ? 8 : 0;

    issue(0, 0);
    for (int kc = 0; kc < G2_NCH; kc++) {
        const int s = kc & 1;
        CPW0();
        __syncthreads();
        if (kc + 1 < G2_NCH) issue(s ^ 1, kc + 1);
        const uint32_t sb = sbase + s * G2_STG;
        #pragma unroll
        for (int ks = 0; ks < 4; ks++) {
            uint32_t b[4][2];
            {
                const uint32_t off0 = bRow * PB + (ks * 16 + bColSel) * 2;
                const uint32_t off1 = off0 + 16 * PB;   // nt pair {2,3}: rows +16
                uint32_t t[4];
                ldm_x4(t, sb + G2_B + off0);
                b[0][0] = t[0]; b[0][1] = t[1]; b[1][0] = t[2]; b[1][1] = t[3];
                ldm_x4(t, sb + G2_B + off1);
                b[2][0] = t[0]; b[2][1] = t[1]; b[3][0] = t[2]; b[3][1] = t[3];
            }
            const int arow = warpM * 64 + (lane & 15);
            const int acol = ks * 16 + ((lane >> 4) << 3);
            #pragma unroll
            for (int mt = 0; mt < 4; mt++) {
                uint32_t a[4];
                ldm_x4(a, sb + G2_A + (arow + mt * 16) * PB + acol * 2);
                #pragma unroll
                for (int nt = 0; nt < 4; nt++) mma16816(acc[mt][nt], a, b[nt]);
            }
        }
    }

    // epilogue: scale by routing weight, scatter to out[pack]
    #pragma unroll
    for (int mt = 0; mt < 4; mt++) {
        #pragma unroll
        for (int rr = 0; rr < 2; rr++) {
            const int lrow = warpM * 64 + mt * 16 + (lane >> 2) + rr * 8;
            const int pack = s_pack[lrow];
            if (pack >= 0) {
                const float w = rw[pack];
                float* fo = out + (size_t)pack * DDIM + n0;
                #pragma unroll
                for (int nt = 0; nt < 4; nt++) {
                    const int col = warpN * 32 + nt * 8 + (lane & 3) * 2;
                    float2 o2;
                    o2.x = acc[mt][nt][rr * 2 + 0] * w;
                    o2.y = acc[mt][nt][rr * 2 + 1] * w;
                    *(float2*)(fo + col) = o2;
                }
            }
        }
    }
}

// ===================== launch ===============================================
extern "C" void kernel_launch(void* const* d_in, const int* in_sizes, int n_in,
                              void* d_out, int out_size) {
    const float* x   = (const float*)d_in[0];
    const float* w0  = (const float*)d_in[1];
    const float* w1  = (const float*)d_in[2];
    const float* w2  = (const float*)d_in[3];
    const int*   sel = (const int*)  d_in[4];
    const float* rw  = (const float*)d_in[5];
    float*       out = (float*)d_out;

    cudaFuncSetAttribute(gemm1_mma, cudaFuncAttributeMaxDynamicSharedMemorySize, G1_SMEM);
    cudaFuncSetAttribute(gemm2_mma, cudaFuncAttributeMaxDynamicSharedMemorySize, G2_SMEM);

    route_kernel<<<1, 256>>>(sel);

    cvt_all<<<(unsigned)(NCVT / 256), 256>>>((const float4*)x, (const float4*)w0,
                                             (const float4*)w1, (const float4*)w2);

    dim3 g1(IDIM / 64, NA / 128, NEXP);    // 22 x 128 x 16
    gemm1_mma<<<g1, 256, G1_SMEM>>>();

    dim3 g2(DDIM / 128, NA / 128, NEXP);   // 16 x 128 x 16
    gemm2_mma<<<g2, 256, G2_SMEM>>>(rw, out);
}